// round 13
// baseline (speedup 1.0000x reference)
#include <cuda_runtime.h>
#include <cstdint>

// out = noise * gamma * sqrt(spread_bits(trunc(x * 2^14))) / 2^14
// spread_bits: bit k of w -> bit 2k, i.e. sum_k 4^k * bit_k = sum_k (2^k*bit_k)^2
// (closed form of the reference's bit-decomposition while-loop)

__device__ __forceinline__ unsigned spread16(unsigned v) {
    v = (v | (v << 8)) & 0x00FF00FFu;
    v = (v | (v << 4)) & 0x0F0F0F0Fu;
    v = (v | (v << 2)) & 0x33333333u;
    v = (v | (v << 1)) & 0x55555555u;
    return v;
}

__device__ __forceinline__ float sigma_elem(float x) {
    int w = (int)(x * 16384.0f);          // trunc toward zero, matches int cast
    unsigned acc = spread16((unsigned)w);
    return sqrtf((float)acc) * (0.05f / 16384.0f);   // gamma / 2^wf_bits
}

// 256-bit vector load/store (sm_100+): LDG.E.256 / STG.E.256, streaming
// (evict-first) policy — every byte is touched exactly once.
__device__ __forceinline__ void ldg256_cs(const float* p, float* r) {
    asm volatile(
        "ld.global.cs.v8.f32 {%0,%1,%2,%3,%4,%5,%6,%7}, [%8];"
        : "=f"(r[0]), "=f"(r[1]), "=f"(r[2]), "=f"(r[3]),
          "=f"(r[4]), "=f"(r[5]), "=f"(r[6]), "=f"(r[7])
        : "l"(p));
}

__device__ __forceinline__ void stg256_cs(float* p, const float* r) {
    asm volatile(
        "st.global.cs.v8.f32 [%0], {%1,%2,%3,%4,%5,%6,%7,%8};"
        :: "l"(p),
           "f"(r[0]), "f"(r[1]), "f"(r[2]), "f"(r[3]),
           "f"(r[4]), "f"(r[5]), "f"(r[6]), "f"(r[7])
        : "memory");
}

// FINAL FORM (best measured: 52.32us kernel, 7.70 TB/s effective = 96% of
// 8 TB/s HBM spec — at the LTS/HBM throughput wall). 256 threads/block, one
// v8 (32B) per thread per array: consecutive threads touch consecutive 32B
// chunks -> 1KB/warp per load instruction, fully coalesced. regs=28 ->
// 8 CTAs/SM, occ ~82%. Compute pipes (alu 35%, fma 19%) fully hidden.
__global__ void __launch_bounds__(256) weight_noise_kernel(
        const float* __restrict__ x,
        const float* __restrict__ noise,
        float* __restrict__ out,
        int n) {
    long long t = (long long)blockIdx.x * blockDim.x + threadIdx.x;
    long long i = t * 8;
    if (i + 8 <= n) {
        float xv[8], nv[8], ov[8];
        ldg256_cs(x + i, xv);
        ldg256_cs(noise + i, nv);
        #pragma unroll
        for (int k = 0; k < 8; k++)
            ov[k] = nv[k] * sigma_elem(xv[k]);
        stg256_cs(out + i, ov);
    } else {
        for (long long j = i; j < n; j++)
            out[j] = noise[j] * sigma_elem(x[j]);
    }
}

extern "C" void kernel_launch(void* const* d_in, const int* in_sizes, int n_in,
                              void* d_out, int out_size) {
    const float* x = (const float*)d_in[0];
    const float* noise = (const float*)d_in[1];
    float* out = (float*)d_out;
    int n = in_sizes[0];                      // 33554432
    int threads = 256;
    long long nthreads = (n + 7) / 8;         // 8 floats per thread
    int blocks = (int)((nthreads + threads - 1) / threads);  // 16384 exact
    weight_noise_kernel<<<blocks, threads>>>(x, noise, out, n);
}

// round 15
// speedup vs baseline: 1.0124x; 1.0124x over previous
#include <cuda_runtime.h>
#include <cstdint>

// out = noise * gamma * sqrt(spread_bits(trunc(x * 2^14))) / 2^14
// spread_bits: bit k of w -> bit 2k, i.e. sum_k 4^k * bit_k = sum_k (2^k*bit_k)^2
// (closed form of the reference's bit-decomposition while-loop)

__device__ __forceinline__ unsigned spread16(unsigned v) {
    v = (v | (v << 8)) & 0x00FF00FFu;
    v = (v | (v << 4)) & 0x0F0F0F0Fu;
    v = (v | (v << 2)) & 0x33333333u;
    v = (v | (v << 1)) & 0x55555555u;
    return v;
}

__device__ __forceinline__ float sigma_elem(float x) {
    int w = (int)(x * 16384.0f);          // trunc toward zero, matches int cast
    unsigned acc = spread16((unsigned)w);
    return sqrtf((float)acc) * (0.05f / 16384.0f);   // gamma / 2^wf_bits
}

// 256-bit vector load/store (sm_100+): LDG.E.256 / STG.E.256, streaming
// (evict-first) policy — every byte is touched exactly once.
__device__ __forceinline__ void ldg256_cs(const float* p, float* r) {
    asm volatile(
        "ld.global.cs.v8.f32 {%0,%1,%2,%3,%4,%5,%6,%7}, [%8];"
        : "=f"(r[0]), "=f"(r[1]), "=f"(r[2]), "=f"(r[3]),
          "=f"(r[4]), "=f"(r[5]), "=f"(r[6]), "=f"(r[7])
        : "l"(p));
}

__device__ __forceinline__ void stg256_cs(float* p, const float* r) {
    asm volatile(
        "st.global.cs.v8.f32 [%0], {%1,%2,%3,%4,%5,%6,%7,%8};"
        :: "l"(p),
           "f"(r[0]), "f"(r[1]), "f"(r[2]), "f"(r[3]),
           "f"(r[4]), "f"(r[5]), "f"(r[6]), "f"(r[7])
        : "memory");
}

// FINAL FORM (best measured: 52.32us kernel, 7.70 TB/s effective = 96% of
// 8 TB/s HBM spec — at the LTS/HBM throughput wall). 256 threads/block, one
// v8 (32B) per thread per array: consecutive threads touch consecutive 32B
// chunks -> 1KB/warp per load instruction, fully coalesced. regs=28 ->
// 8 CTAs/SM, occ ~80%. Compute pipes (alu 36%, fma 20%) fully hidden.
// Measured equal-or-worse alternatives: float4 path (55us), batching x4
// (55us, occ drop), 512-thread blocks (52.8-53.8us), persistent+double-
// buffer (54.6us, regs 64), NC loads (53.4us), launch-bounds hints (53.8us).
__global__ void __launch_bounds__(256) weight_noise_kernel(
        const float* __restrict__ x,
        const float* __restrict__ noise,
        float* __restrict__ out,
        int n) {
    long long t = (long long)blockIdx.x * blockDim.x + threadIdx.x;
    long long i = t * 8;
    if (i + 8 <= n) {
        float xv[8], nv[8], ov[8];
        ldg256_cs(x + i, xv);
        ldg256_cs(noise + i, nv);
        #pragma unroll
        for (int k = 0; k < 8; k++)
            ov[k] = nv[k] * sigma_elem(xv[k]);
        stg256_cs(out + i, ov);
    } else {
        for (long long j = i; j < n; j++)
            out[j] = noise[j] * sigma_elem(x[j]);
    }
}

extern "C" void kernel_launch(void* const* d_in, const int* in_sizes, int n_in,
                              void* d_out, int out_size) {
    const float* x = (const float*)d_in[0];
    const float* noise = (const float*)d_in[1];
    float* out = (float*)d_out;
    int n = in_sizes[0];                      // 33554432
    int threads = 256;
    long long nthreads = (n + 7) / 8;         // 8 floats per thread
    int blocks = (int)((nthreads + threads - 1) / threads);  // 16384 exact
    weight_noise_kernel<<<blocks, threads>>>(x, noise, out, n);
}